// round 16
// baseline (speedup 1.0000x reference)
#include <cuda_runtime.h>
#include <cuda_bf16.h>
#include <cuda_fp16.h>

#define EMB 16
#define MAXN 200000

// Scratch (device globals — no allocation allowed)
__device__ uint4  g_left_h[MAXN * 2];    // [N_LEFT, 16] half
__device__ uint4  g_right_h[MAXN * 2];   // [N_RIGHT, 16] half
__device__ float4 g_agg[MAXN * 4];       // [N_RIGHT, 16] fp32 sum of relu(pre)
__device__ float  g_deg[MAXN];           // per-right-node degree (float)
__device__ float  g_Wc[EMB * EMB];       // W1a @ W_post  (folded)
__device__ float  g_bc[EMB];             // W1a @ b_post + b_out1

// ---------------------------------------------------------------------------
// Kernel 1 (fused): node transforms (2 nodes/thread) -> fp16 tables
//                   + zero-init of g_agg/g_deg + weight fold (block 0).
// ---------------------------------------------------------------------------
__global__ void node_transform_kernel(const float4* __restrict__ left,
                                      const float4* __restrict__ right,
                                      const float4* __restrict__ W_left,
                                      const float* __restrict__ b_left,
                                      const float4* __restrict__ W_right,
                                      const float* __restrict__ W_post,
                                      const float* __restrict__ b_post,
                                      const float* __restrict__ W_out1,
                                      const float* __restrict__ b_out1,
                                      int n_left, int n_right) {
    __shared__ float4 sWl[EMB * 4];
    __shared__ float4 sWr[EMB * 4];
    __shared__ float  sbl[EMB];
    for (int i = threadIdx.x; i < EMB * 4; i += blockDim.x) {
        sWl[i] = W_left[i];
        sWr[i] = W_right[i];
    }
    if (threadIdx.x < EMB) sbl[threadIdx.x] = b_left[threadIdx.x];
    __syncthreads();

    // Fold (block 0 only): Wc = W1a @ W_post ; bc = W1a @ b_post + b_out1
    if (blockIdx.x == 0) {
        int tid = threadIdx.x;           // 256 threads: (j,k)
        int j = tid >> 4;
        int k = tid & 15;
        float acc = 0.0f;
#pragma unroll
        for (int m = 0; m < EMB; m++)
            acc = fmaf(W_out1[j * 32 + m], W_post[m * EMB + k], acc);
        g_Wc[j * EMB + k] = acc;
        if (k == 0) {
            float b = b_out1[j];
#pragma unroll
            for (int m = 0; m < EMB; m++)
                b = fmaf(W_out1[j * 32 + m], b_post[m], b);
            g_bc[j] = b;
        }
    }

    int nL2 = (n_left + 1) >> 1;
    int nR2 = (n_right + 1) >> 1;
    int t = blockIdx.x * blockDim.x + threadIdx.x;

    if (t >= nL2 + nR2) {
        // zero-init range: one thread per 2 right nodes
        int z = t - (nL2 + nR2);
        if (z < nR2) {
            int n0 = 2 * z;
            float4 zero = make_float4(0.0f, 0.0f, 0.0f, 0.0f);
            float4* ap = g_agg + (size_t)n0 * 4;
            ap[0] = zero; ap[1] = zero; ap[2] = zero; ap[3] = zero;
            g_deg[n0] = 0.0f;
            if (n0 + 1 < n_right) {
                ap[4] = zero; ap[5] = zero; ap[6] = zero; ap[7] = zero;
                g_deg[n0 + 1] = 0.0f;
            }
        }
        return;
    }

    bool is_left = (t < nL2);
    int base = is_left ? (2 * t) : (2 * (t - nL2));
    int count = is_left ? n_left : n_right;
    const float4* srcb = is_left ? left : right;
    uint4* dstb = is_left ? g_left_h : g_right_h;
    const float4* W = is_left ? sWl : sWr;
    bool has1 = (base + 1 < count);

    float4 x0[4], x1[4];
#pragma unroll
    for (int q = 0; q < 4; q++) x0[q] = srcb[(size_t)base * 4 + q];
    if (has1) {
#pragma unroll
        for (int q = 0; q < 4; q++) x1[q] = srcb[(size_t)(base + 1) * 4 + q];
    } else {
#pragma unroll
        for (int q = 0; q < 4; q++) x1[q] = x0[q];
    }

    float y0[EMB], y1[EMB];
#pragma unroll
    for (int j = 0; j < EMB; j++) {
        float b = is_left ? sbl[j] : 0.0f;
        float a0 = b, a1 = b;
#pragma unroll
        for (int q = 0; q < 4; q++) {
            float4 w = W[j * 4 + q];   // one LDS.128 serves both nodes
            a0 = fmaf(x0[q].x, w.x, a0);
            a0 = fmaf(x0[q].y, w.y, a0);
            a0 = fmaf(x0[q].z, w.z, a0);
            a0 = fmaf(x0[q].w, w.w, a0);
            a1 = fmaf(x1[q].x, w.x, a1);
            a1 = fmaf(x1[q].y, w.y, a1);
            a1 = fmaf(x1[q].z, w.z, a1);
            a1 = fmaf(x1[q].w, w.w, a1);
        }
        y0[j] = a0; y1[j] = a1;
    }

#pragma unroll
    for (int h = 0; h < 2; h++) {
        uint4 o;
        __half2 h0 = __floats2half2_rn(y0[8 * h + 0], y0[8 * h + 1]);
        __half2 h1 = __floats2half2_rn(y0[8 * h + 2], y0[8 * h + 3]);
        __half2 h2 = __floats2half2_rn(y0[8 * h + 4], y0[8 * h + 5]);
        __half2 h3 = __floats2half2_rn(y0[8 * h + 6], y0[8 * h + 7]);
        o.x = *(unsigned int*)&h0;
        o.y = *(unsigned int*)&h1;
        o.z = *(unsigned int*)&h2;
        o.w = *(unsigned int*)&h3;
        dstb[(size_t)base * 2 + h] = o;
    }
    if (has1) {
#pragma unroll
        for (int h = 0; h < 2; h++) {
            uint4 o;
            __half2 h0 = __floats2half2_rn(y1[8 * h + 0], y1[8 * h + 1]);
            __half2 h1 = __floats2half2_rn(y1[8 * h + 2], y1[8 * h + 3]);
            __half2 h2 = __floats2half2_rn(y1[8 * h + 4], y1[8 * h + 5]);
            __half2 h3 = __floats2half2_rn(y1[8 * h + 6], y1[8 * h + 7]);
            o.x = *(unsigned int*)&h0;
            o.y = *(unsigned int*)&h1;
            o.z = *(unsigned int*)&h2;
            o.w = *(unsigned int*)&h3;
            dstb[(size_t)(base + 1) * 2 + h] = o;
        }
    }
}

// ---------------------------------------------------------------------------
// Kernel 2: edge kernel — EXACT R5/R9 structure (empirically fastest).
// ---------------------------------------------------------------------------
__global__ void edge_kernel(const int* __restrict__ eidx,          // [2, E] int32
                            const float* __restrict__ efeat,       // [E]
                            const float4* __restrict__ W_edge4,    // 16 floats
                            int E) {
    long long t = (long long)blockIdx.x * blockDim.x + threadIdx.x;
    int e = (int)(t >> 1);
    if (e >= E) return;
    int j = (int)(t & 1);

    int li = eidx[e];
    int ri = eidx[(size_t)E + e];
    float w = efeat[e];

    uint4 Lu = g_left_h[(size_t)li * 2 + j];
    uint4 Ru = g_right_h[(size_t)ri * 2 + j];
    float4 We0 = W_edge4[2 * j];
    float4 We1 = W_edge4[2 * j + 1];

    float2 l0 = __half22float2(*(__half2*)&Lu.x);
    float2 l1 = __half22float2(*(__half2*)&Lu.y);
    float2 l2 = __half22float2(*(__half2*)&Lu.z);
    float2 l3 = __half22float2(*(__half2*)&Lu.w);
    float2 r0 = __half22float2(*(__half2*)&Ru.x);
    float2 r1 = __half22float2(*(__half2*)&Ru.y);
    float2 r2 = __half22float2(*(__half2*)&Ru.z);
    float2 r3 = __half22float2(*(__half2*)&Ru.w);

    float p0 = fmaxf(fmaf(w, We0.x, l0.x + r0.x), 0.0f);
    float p1 = fmaxf(fmaf(w, We0.y, l0.y + r0.y), 0.0f);
    float p2 = fmaxf(fmaf(w, We0.z, l1.x + r1.x), 0.0f);
    float p3 = fmaxf(fmaf(w, We0.w, l1.y + r1.y), 0.0f);
    float p4 = fmaxf(fmaf(w, We1.x, l2.x + r2.x), 0.0f);
    float p5 = fmaxf(fmaf(w, We1.y, l2.y + r2.y), 0.0f);
    float p6 = fmaxf(fmaf(w, We1.z, l3.x + r3.x), 0.0f);
    float p7 = fmaxf(fmaf(w, We1.w, l3.y + r3.y), 0.0f);

    float4* dst = g_agg + (size_t)ri * 4 + 2 * j;
    asm volatile("red.global.add.v4.f32 [%0], {%1, %2, %3, %4};"
                 :: "l"(dst), "f"(p0), "f"(p1), "f"(p2), "f"(p3)
                 : "memory");
    asm volatile("red.global.add.v4.f32 [%0], {%1, %2, %3, %4};"
                 :: "l"(dst + 1), "f"(p4), "f"(p5), "f"(p6), "f"(p7)
                 : "memory");
    if (j == 0) {
        asm volatile("red.global.add.f32 [%0], %1;"
                     :: "l"(g_deg + ri), "f"(1.0f)
                     : "memory");
    }
}

// ---------------------------------------------------------------------------
// Kernel 3: per-right-node tail, 2 NODES PER THREAD (amortize weight LDS).
//   a   = relu(agg @ Wf.T + d*bf)
//   h   = relu(a @ Wc.T + right @ W1b.T + bc)
//   out = h @ W2.T + b2
// ---------------------------------------------------------------------------
__global__ __launch_bounds__(128)
void post_kernel(const float4* __restrict__ rightf,
                 const float4* __restrict__ W_final, const float* __restrict__ b_final,
                 const float* __restrict__ W_out1,   // [16][32] raw (for W1b half)
                 const float4* __restrict__ W_out2,  const float* __restrict__ b_out2,
                 float4* __restrict__ out, int n_right) {
    __shared__ float4 sWf[64], sWc[64], sW1b[64], sW2[64];
    __shared__ float  sbf[16], sbc[16], sb2[16];
    for (int i = threadIdx.x; i < 64; i += blockDim.x) {
        sWf[i] = W_final[i];
        sWc[i] = *(const float4*)&g_Wc[i * 4];
        sW2[i] = W_out2[i];
        int j = i >> 2, q = i & 3;
        sW1b[i] = *(const float4*)&W_out1[j * 32 + 16 + q * 4];
    }
    if (threadIdx.x < 16) {
        sbf[threadIdx.x] = b_final[threadIdx.x];
        sbc[threadIdx.x] = g_bc[threadIdx.x];
        sb2[threadIdx.x] = b_out2[threadIdx.x];
    }
    __syncthreads();

    int idx = blockIdx.x * blockDim.x + threadIdx.x;
    int r0 = 2 * idx;
    if (r0 >= n_right) return;
    bool has1 = (r0 + 1 < n_right);
    int r1 = has1 ? (r0 + 1) : r0;

    float4 S0[4], S1[4], R0[4], R1[4];
#pragma unroll
    for (int q = 0; q < 4; q++) {
        S0[q] = g_agg[(size_t)r0 * 4 + q];
        S1[q] = g_agg[(size_t)r1 * 4 + q];
        R0[q] = rightf[(size_t)r0 * 4 + q];
        R1[q] = rightf[(size_t)r1 * 4 + q];
    }
    float d0 = g_deg[r0];
    float d1 = g_deg[r1];

    // a = relu(S @ Wf.T + d*bf)
    float4 a0[4], a1[4];
#pragma unroll
    for (int q = 0; q < 4; q++) {
        float t0[4], t1[4];
#pragma unroll
        for (int c = 0; c < 4; c++) {
            int j = 4 * q + c;
            float bfj = sbf[j];
            float acc0 = d0 * bfj;
            float acc1 = d1 * bfj;
#pragma unroll
            for (int p = 0; p < 4; p++) {
                float4 wv = sWf[j * 4 + p];
                acc0 = fmaf(S0[p].x, wv.x, acc0);
                acc0 = fmaf(S0[p].y, wv.y, acc0);
                acc0 = fmaf(S0[p].z, wv.z, acc0);
                acc0 = fmaf(S0[p].w, wv.w, acc0);
                acc1 = fmaf(S1[p].x, wv.x, acc1);
                acc1 = fmaf(S1[p].y, wv.y, acc1);
                acc1 = fmaf(S1[p].z, wv.z, acc1);
                acc1 = fmaf(S1[p].w, wv.w, acc1);
            }
            t0[c] = fmaxf(acc0, 0.0f);
            t1[c] = fmaxf(acc1, 0.0f);
        }
        a0[q].x = t0[0]; a0[q].y = t0[1]; a0[q].z = t0[2]; a0[q].w = t0[3];
        a1[q].x = t1[0]; a1[q].y = t1[1]; a1[q].z = t1[2]; a1[q].w = t1[3];
    }

    // h = relu(a @ Wc.T + R @ W1b.T + bc)
    float4 h0[4], h1[4];
#pragma unroll
    for (int q = 0; q < 4; q++) {
        float t0[4], t1[4];
#pragma unroll
        for (int c = 0; c < 4; c++) {
            int j = 4 * q + c;
            float bcj = sbc[j];
            float acc0 = bcj, acc1 = bcj;
#pragma unroll
            for (int p = 0; p < 4; p++) {
                float4 wv = sWc[j * 4 + p];
                acc0 = fmaf(a0[p].x, wv.x, acc0);
                acc0 = fmaf(a0[p].y, wv.y, acc0);
                acc0 = fmaf(a0[p].z, wv.z, acc0);
                acc0 = fmaf(a0[p].w, wv.w, acc0);
                acc1 = fmaf(a1[p].x, wv.x, acc1);
                acc1 = fmaf(a1[p].y, wv.y, acc1);
                acc1 = fmaf(a1[p].z, wv.z, acc1);
                acc1 = fmaf(a1[p].w, wv.w, acc1);
            }
#pragma unroll
            for (int p = 0; p < 4; p++) {
                float4 wv = sW1b[j * 4 + p];
                acc0 = fmaf(R0[p].x, wv.x, acc0);
                acc0 = fmaf(R0[p].y, wv.y, acc0);
                acc0 = fmaf(R0[p].z, wv.z, acc0);
                acc0 = fmaf(R0[p].w, wv.w, acc0);
                acc1 = fmaf(R1[p].x, wv.x, acc1);
                acc1 = fmaf(R1[p].y, wv.y, acc1);
                acc1 = fmaf(R1[p].z, wv.z, acc1);
                acc1 = fmaf(R1[p].w, wv.w, acc1);
            }
            t0[c] = fmaxf(acc0, 0.0f);
            t1[c] = fmaxf(acc1, 0.0f);
        }
        h0[q].x = t0[0]; h0[q].y = t0[1]; h0[q].z = t0[2]; h0[q].w = t0[3];
        h1[q].x = t1[0]; h1[q].y = t1[1]; h1[q].z = t1[2]; h1[q].w = t1[3];
    }

    // out = h @ W2.T + b2
#pragma unroll
    for (int q = 0; q < 4; q++) {
        float t0[4], t1[4];
#pragma unroll
        for (int c = 0; c < 4; c++) {
            int j = 4 * q + c;
            float b2j = sb2[j];
            float acc0 = b2j, acc1 = b2j;
#pragma unroll
            for (int p = 0; p < 4; p++) {
                float4 wv = sW2[j * 4 + p];
                acc0 = fmaf(h0[p].x, wv.x, acc0);
                acc0 = fmaf(h0[p].y, wv.y, acc0);
                acc0 = fmaf(h0[p].z, wv.z, acc0);
                acc0 = fmaf(h0[p].w, wv.w, acc0);
                acc1 = fmaf(h1[p].x, wv.x, acc1);
                acc1 = fmaf(h1[p].y, wv.y, acc1);
                acc1 = fmaf(h1[p].z, wv.z, acc1);
                acc1 = fmaf(h1[p].w, wv.w, acc1);
            }
            t0[c] = acc0;
            t1[c] = acc1;
        }
        float4 y0, y1;
        y0.x = t0[0]; y0.y = t0[1]; y0.z = t0[2]; y0.w = t0[3];
        y1.x = t1[0]; y1.y = t1[1]; y1.z = t1[2]; y1.w = t1[3];
        out[(size_t)r0 * 4 + q] = y0;
        if (has1) out[(size_t)r1 * 4 + q] = y1;
    }
}

// ---------------------------------------------------------------------------
extern "C" void kernel_launch(void* const* d_in, const int* in_sizes, int n_in,
                              void* d_out, int out_size) {
    const float* left    = (const float*)d_in[0];
    const float* efeat   = (const float*)d_in[1];
    const float* right   = (const float*)d_in[2];
    const int*   eidx    = (const int*)d_in[3];   // int32: JAX x64 disabled
    const float* W_left  = (const float*)d_in[4];
    const float* b_left  = (const float*)d_in[5];
    const float* W_edge  = (const float*)d_in[6];
    const float* W_right = (const float*)d_in[7];
    const float* W_final = (const float*)d_in[8];
    const float* b_final = (const float*)d_in[9];
    const float* W_post  = (const float*)d_in[10];
    const float* b_post  = (const float*)d_in[11];
    const float* W_out1  = (const float*)d_in[12];
    const float* b_out1  = (const float*)d_in[13];
    const float* W_out2  = (const float*)d_in[14];
    const float* b_out2  = (const float*)d_in[15];
    float* out = (float*)d_out;

    int n_left  = in_sizes[0] / EMB;
    int n_right = in_sizes[2] / EMB;
    int E       = in_sizes[1];

    int nL2 = (n_left + 1) / 2;
    int nR2 = (n_right + 1) / 2;
    int total_threads = nL2 + nR2 + nR2;   // node pairs + zero-init pairs
    node_transform_kernel<<<(total_threads + 255) / 256, 256>>>(
        (const float4*)left, (const float4*)right, (const float4*)W_left, b_left,
        (const float4*)W_right, W_post, b_post, W_out1, b_out1,
        n_left, n_right);

    long long edge_threads = (long long)E * 2;
    int edge_blocks = (int)((edge_threads + 255) / 256);
    edge_kernel<<<edge_blocks, 256>>>(eidx, efeat, (const float4*)W_edge, E);

    int post_threads = (n_right + 1) / 2;
    post_kernel<<<(post_threads + 127) / 128, 128>>>(
        (const float4*)right,
        (const float4*)W_final, b_final,
        W_out1,
        (const float4*)W_out2, b_out2,
        (float4*)out, n_right);
}

// round 17
// speedup vs baseline: 1.0350x; 1.0350x over previous
#include <cuda_runtime.h>
#include <cuda_bf16.h>
#include <cuda_fp16.h>

#define EMB 16
#define MAXN 200000

// Scratch (device globals — no allocation allowed)
__device__ uint4  g_left_h[MAXN * 2];    // [N_LEFT, 16] half
__device__ uint4  g_right_h[MAXN * 2];   // [N_RIGHT, 16] half
__device__ float4 g_agg[MAXN * 4];       // [N_RIGHT, 16] fp32 sum of relu(pre)
__device__ float  g_deg[MAXN];           // per-right-node degree (float)
__device__ float  g_Wc[EMB * EMB];       // W1a @ W_post  (folded)
__device__ float  g_bc[EMB];             // W1a @ b_post + b_out1

// ---------------------------------------------------------------------------
// Kernel 1 (fused, R15 proven): node transforms -> fp16 tables
//                   + zero-init of g_agg/g_deg + weight fold (block 0).
// ---------------------------------------------------------------------------
__global__ void node_transform_kernel(const float4* __restrict__ left,
                                      const float4* __restrict__ right,
                                      const float4* __restrict__ W_left,
                                      const float* __restrict__ b_left,
                                      const float4* __restrict__ W_right,
                                      const float* __restrict__ W_post,
                                      const float* __restrict__ b_post,
                                      const float* __restrict__ W_out1,
                                      const float* __restrict__ b_out1,
                                      int n_left, int n_right) {
    __shared__ float4 sWl[EMB * 4];
    __shared__ float4 sWr[EMB * 4];
    __shared__ float  sbl[EMB];
    for (int i = threadIdx.x; i < EMB * 4; i += blockDim.x) {
        sWl[i] = W_left[i];
        sWr[i] = W_right[i];
    }
    if (threadIdx.x < EMB) sbl[threadIdx.x] = b_left[threadIdx.x];
    __syncthreads();

    // Fold (block 0 only): Wc = W1a @ W_post ; bc = W1a @ b_post + b_out1
    if (blockIdx.x == 0) {
        int tid = threadIdx.x;           // 256 threads: (j,k)
        int j = tid >> 4;
        int k = tid & 15;
        float acc = 0.0f;
#pragma unroll
        for (int m = 0; m < EMB; m++)
            acc = fmaf(W_out1[j * 32 + m], W_post[m * EMB + k], acc);
        g_Wc[j * EMB + k] = acc;
        if (k == 0) {
            float b = b_out1[j];
#pragma unroll
            for (int m = 0; m < EMB; m++)
                b = fmaf(W_out1[j * 32 + m], b_post[m], b);
            g_bc[j] = b;
        }
    }

    int total_nodes = n_left + n_right;
    int t = blockIdx.x * blockDim.x + threadIdx.x;

    if (t >= total_nodes) {
        // zero-init range: one thread per right node
        int z = t - total_nodes;
        if (z < n_right) {
            float4 zero = make_float4(0.0f, 0.0f, 0.0f, 0.0f);
            float4* ap = g_agg + (size_t)z * 4;
            ap[0] = zero; ap[1] = zero; ap[2] = zero; ap[3] = zero;
            g_deg[z] = 0.0f;
        }
        return;
    }

    bool is_left = (t < n_left);
    int node = is_left ? t : (t - n_left);
    const float4* src = is_left ? (left + (size_t)node * 4) : (right + (size_t)node * 4);
    uint4* dst = is_left ? (g_left_h + (size_t)node * 2) : (g_right_h + (size_t)node * 2);
    const float4* W = is_left ? sWl : sWr;

    float4 x[4];
#pragma unroll
    for (int q = 0; q < 4; q++) x[q] = src[q];

    float y[EMB];
#pragma unroll
    for (int j = 0; j < EMB; j++) {
        float a = is_left ? sbl[j] : 0.0f;
#pragma unroll
        for (int q = 0; q < 4; q++) {
            float4 w = W[j * 4 + q];
            a = fmaf(x[q].x, w.x, a);
            a = fmaf(x[q].y, w.y, a);
            a = fmaf(x[q].z, w.z, a);
            a = fmaf(x[q].w, w.w, a);
        }
        y[j] = a;
    }

#pragma unroll
    for (int h = 0; h < 2; h++) {
        uint4 o;
        __half2 h0 = __floats2half2_rn(y[8 * h + 0], y[8 * h + 1]);
        __half2 h1 = __floats2half2_rn(y[8 * h + 2], y[8 * h + 3]);
        __half2 h2 = __floats2half2_rn(y[8 * h + 4], y[8 * h + 5]);
        __half2 h3 = __floats2half2_rn(y[8 * h + 6], y[8 * h + 7]);
        o.x = *(unsigned int*)&h0;
        o.y = *(unsigned int*)&h1;
        o.z = *(unsigned int*)&h2;
        o.w = *(unsigned int*)&h3;
        dst[h] = o;
    }
}

// ---------------------------------------------------------------------------
// Kernel 2: edge kernel — EXACT R5/R9 structure (empirically fastest).
// ---------------------------------------------------------------------------
__global__ void edge_kernel(const int* __restrict__ eidx,          // [2, E] int32
                            const float* __restrict__ efeat,       // [E]
                            const float4* __restrict__ W_edge4,    // 16 floats
                            int E) {
    long long t = (long long)blockIdx.x * blockDim.x + threadIdx.x;
    int e = (int)(t >> 1);
    if (e >= E) return;
    int j = (int)(t & 1);

    int li = eidx[e];
    int ri = eidx[(size_t)E + e];
    float w = efeat[e];

    uint4 Lu = g_left_h[(size_t)li * 2 + j];
    uint4 Ru = g_right_h[(size_t)ri * 2 + j];
    float4 We0 = W_edge4[2 * j];
    float4 We1 = W_edge4[2 * j + 1];

    float2 l0 = __half22float2(*(__half2*)&Lu.x);
    float2 l1 = __half22float2(*(__half2*)&Lu.y);
    float2 l2 = __half22float2(*(__half2*)&Lu.z);
    float2 l3 = __half22float2(*(__half2*)&Lu.w);
    float2 r0 = __half22float2(*(__half2*)&Ru.x);
    float2 r1 = __half22float2(*(__half2*)&Ru.y);
    float2 r2 = __half22float2(*(__half2*)&Ru.z);
    float2 r3 = __half22float2(*(__half2*)&Ru.w);

    float p0 = fmaxf(fmaf(w, We0.x, l0.x + r0.x), 0.0f);
    float p1 = fmaxf(fmaf(w, We0.y, l0.y + r0.y), 0.0f);
    float p2 = fmaxf(fmaf(w, We0.z, l1.x + r1.x), 0.0f);
    float p3 = fmaxf(fmaf(w, We0.w, l1.y + r1.y), 0.0f);
    float p4 = fmaxf(fmaf(w, We1.x, l2.x + r2.x), 0.0f);
    float p5 = fmaxf(fmaf(w, We1.y, l2.y + r2.y), 0.0f);
    float p6 = fmaxf(fmaf(w, We1.z, l3.x + r3.x), 0.0f);
    float p7 = fmaxf(fmaf(w, We1.w, l3.y + r3.y), 0.0f);

    float4* dst = g_agg + (size_t)ri * 4 + 2 * j;
    asm volatile("red.global.add.v4.f32 [%0], {%1, %2, %3, %4};"
                 :: "l"(dst), "f"(p0), "f"(p1), "f"(p2), "f"(p3)
                 : "memory");
    asm volatile("red.global.add.v4.f32 [%0], {%1, %2, %3, %4};"
                 :: "l"(dst + 1), "f"(p4), "f"(p5), "f"(p6), "f"(p7)
                 : "memory");
    if (j == 0) {
        asm volatile("red.global.add.f32 [%0], %1;"
                     :: "l"(g_deg + ri), "f"(1.0f)
                     : "memory");
    }
}

// ---------------------------------------------------------------------------
// Kernel 3: per-right-node tail, 2 THREADS PER NODE (cross-partial pattern).
// Thread jj of a pair owns output channels [8jj, 8jj+8) and input quarters
// kq=2jj..2jj+1 of intermediate vectors. All register arrays static-indexed;
// jj appears only in shared/global addresses. One shfl.xor(1) per stage.
// ---------------------------------------------------------------------------
__global__ __launch_bounds__(128)
void post_kernel(const float4* __restrict__ rightf,
                 const float4* __restrict__ W_final, const float* __restrict__ b_final,
                 const float* __restrict__ W_out1,   // [16][32] raw (for W1b half)
                 const float4* __restrict__ W_out2,  const float* __restrict__ b_out2,
                 float4* __restrict__ out, int n_right) {
    __shared__ float4 sWf[64], sWc[64], sW1b[64], sW2[64];
    __shared__ float  sbf[16], sbc[16], sb2[16];
    for (int i = threadIdx.x; i < 64; i += blockDim.x) {
        sWf[i] = W_final[i];
        sWc[i] = *(const float4*)&g_Wc[i * 4];
        sW2[i] = W_out2[i];
        int j = i >> 2, q = i & 3;
        sW1b[i] = *(const float4*)&W_out1[j * 32 + 16 + q * 4];
    }
    if (threadIdx.x < 16) {
        sbf[threadIdx.x] = b_final[threadIdx.x];
        sbc[threadIdx.x] = g_bc[threadIdx.x];
        sb2[threadIdx.x] = b_out2[threadIdx.x];
    }
    __syncthreads();

    int idx = blockIdx.x * blockDim.x + threadIdx.x;
    int rr = idx >> 1;
    int jj = idx & 1;
    if (rr >= n_right) return;
    unsigned mask = __activemask();   // pairs exit together; xor-1 stays in pair

    int jbase = 8 * jj;   // own output-channel base
    int kq    = 2 * jj;   // own input-quarter base

    // Full S (both threads; 64B L2 line, broadcast)
    float4 S[4];
#pragma unroll
    for (int q = 0; q < 4; q++) S[q] = g_agg[(size_t)rr * 4 + q];
    float d = g_deg[rr];

    // Own half of R (input role); quarters kq, kq+1
    float4 Rh[2];
    Rh[0] = rightf[(size_t)rr * 4 + kq];
    Rh[1] = rightf[(size_t)rr * 4 + kq + 1];

    // Stage a: own 8 outputs over full 16 inputs (no shfl needed)
    float a_own[8];
#pragma unroll
    for (int c = 0; c < 8; c++) {
        int j = jbase + c;
        float acc = d * sbf[j];
#pragma unroll
        for (int p = 0; p < 4; p++) {
            float4 wv = sWf[j * 4 + p];
            acc = fmaf(S[p].x, wv.x, acc);
            acc = fmaf(S[p].y, wv.y, acc);
            acc = fmaf(S[p].z, wv.z, acc);
            acc = fmaf(S[p].w, wv.w, acc);
        }
        a_own[c] = fmaxf(acc, 0.0f);
    }

    // Stage h: cross-partial. Own inputs: a_own (quarters kq..) and Rh.
    float Ps[8], Pc[8];
#pragma unroll
    for (int c = 0; c < 8; c++) {
        int js = jbase + c;            // own output
        int jc = (8 - jbase) + c;      // partner's output
        float accS = 0.0f, accC = 0.0f;
#pragma unroll
        for (int p = 0; p < 2; p++) {
            float4 ws = sWc[js * 4 + kq + p];
            float4 wc = sWc[jc * 4 + kq + p];
            accS = fmaf(a_own[4 * p + 0], ws.x, accS);
            accS = fmaf(a_own[4 * p + 1], ws.y, accS);
            accS = fmaf(a_own[4 * p + 2], ws.z, accS);
            accS = fmaf(a_own[4 * p + 3], ws.w, accS);
            accC = fmaf(a_own[4 * p + 0], wc.x, accC);
            accC = fmaf(a_own[4 * p + 1], wc.y, accC);
            accC = fmaf(a_own[4 * p + 2], wc.z, accC);
            accC = fmaf(a_own[4 * p + 3], wc.w, accC);
        }
#pragma unroll
        for (int p = 0; p < 2; p++) {
            float4 ws = sW1b[js * 4 + kq + p];
            float4 wc = sW1b[jc * 4 + kq + p];
            accS = fmaf(Rh[p].x, ws.x, accS);
            accS = fmaf(Rh[p].y, ws.y, accS);
            accS = fmaf(Rh[p].z, ws.z, accS);
            accS = fmaf(Rh[p].w, ws.w, accS);
            accC = fmaf(Rh[p].x, wc.x, accC);
            accC = fmaf(Rh[p].y, wc.y, accC);
            accC = fmaf(Rh[p].z, wc.z, accC);
            accC = fmaf(Rh[p].w, wc.w, accC);
        }
        Ps[c] = accS;
        Pc[c] = accC;
    }
    float h_own[8];
#pragma unroll
    for (int c = 0; c < 8; c++) {
        float tot = Ps[c] + __shfl_xor_sync(mask, Pc[c], 1);
        h_own[c] = fmaxf(tot + sbc[jbase + c], 0.0f);
    }

    // Stage out: cross-partial over h (own quarters kq..).
    float Qs[8], Qc[8];
#pragma unroll
    for (int c = 0; c < 8; c++) {
        int js = jbase + c;
        int jc = (8 - jbase) + c;
        float accS = 0.0f, accC = 0.0f;
#pragma unroll
        for (int p = 0; p < 2; p++) {
            float4 ws = sW2[js * 4 + kq + p];
            float4 wc = sW2[jc * 4 + kq + p];
            accS = fmaf(h_own[4 * p + 0], ws.x, accS);
            accS = fmaf(h_own[4 * p + 1], ws.y, accS);
            accS = fmaf(h_own[4 * p + 2], ws.z, accS);
            accS = fmaf(h_own[4 * p + 3], ws.w, accS);
            accC = fmaf(h_own[4 * p + 0], wc.x, accC);
            accC = fmaf(h_own[4 * p + 1], wc.y, accC);
            accC = fmaf(h_own[4 * p + 2], wc.z, accC);
            accC = fmaf(h_own[4 * p + 3], wc.w, accC);
        }
        Qs[c] = accS;
        Qc[c] = accC;
    }
    float o_own[8];
#pragma unroll
    for (int c = 0; c < 8; c++) {
        float tot = Qs[c] + __shfl_xor_sync(mask, Qc[c], 1);
        o_own[c] = tot + sb2[jbase + c];
    }

    // Write own 8 output channels (quarters kq, kq+1 of the node's row)
    float4 y0, y1;
    y0.x = o_own[0]; y0.y = o_own[1]; y0.z = o_own[2]; y0.w = o_own[3];
    y1.x = o_own[4]; y1.y = o_own[5]; y1.z = o_own[6]; y1.w = o_own[7];
    out[(size_t)rr * 4 + kq]     = y0;
    out[(size_t)rr * 4 + kq + 1] = y1;
}

// ---------------------------------------------------------------------------
extern "C" void kernel_launch(void* const* d_in, const int* in_sizes, int n_in,
                              void* d_out, int out_size) {
    const float* left    = (const float*)d_in[0];
    const float* efeat   = (const float*)d_in[1];
    const float* right   = (const float*)d_in[2];
    const int*   eidx    = (const int*)d_in[3];   // int32: JAX x64 disabled
    const float* W_left  = (const float*)d_in[4];
    const float* b_left  = (const float*)d_in[5];
    const float* W_edge  = (const float*)d_in[6];
    const float* W_right = (const float*)d_in[7];
    const float* W_final = (const float*)d_in[8];
    const float* b_final = (const float*)d_in[9];
    const float* W_post  = (const float*)d_in[10];
    const float* b_post  = (const float*)d_in[11];
    const float* W_out1  = (const float*)d_in[12];
    const float* b_out1  = (const float*)d_in[13];
    const float* W_out2  = (const float*)d_in[14];
    const float* b_out2  = (const float*)d_in[15];
    float* out = (float*)d_out;

    int n_left  = in_sizes[0] / EMB;
    int n_right = in_sizes[2] / EMB;
    int E       = in_sizes[1];

    int total_threads = n_left + n_right + n_right;   // nodes + zero-init range
    node_transform_kernel<<<(total_threads + 255) / 256, 256>>>(
        (const float4*)left, (const float4*)right, (const float4*)W_left, b_left,
        (const float4*)W_right, W_post, b_post, W_out1, b_out1,
        n_left, n_right);

    long long edge_threads = (long long)E * 2;
    int edge_blocks = (int)((edge_threads + 255) / 256);
    edge_kernel<<<edge_blocks, 256>>>(eidx, efeat, (const float4*)W_edge, E);

    long long post_threads = (long long)n_right * 2;
    post_kernel<<<(int)((post_threads + 127) / 128), 128>>>(
        (const float4*)right,
        (const float4*)W_final, b_final,
        W_out1,
        (const float4*)W_out2, b_out2,
        (float4*)out, n_right);
}